// round 5
// baseline (speedup 1.0000x reference)
#include <cuda_runtime.h>
#include <cuda_bf16.h>
#include <cuda_fp8.h>
#include <math.h>
#include <stdint.h>

#define BATCH 4
#define SEQ   2048
#define HID   2048
#define INTER 5504
#define MROWS (BATCH * SEQ)            // 8192

// lo/hi fp8 scaling (powers of 2, exact)
#define S_LO_A 512.0f                  // 2^9  : A-side lo
#define S_HI_B 64.0f                   // 2^6  : B-side hi
#define S_LO_B 32768.0f                // 2^15 : B-side lo
#define INV_CROSS (1.0f / 32768.0f)    // unscale for cross accumulator

// ---------------------------------------------------------------------------
// Scratch (device globals; no allocation allowed)
// ---------------------------------------------------------------------------
__device__ __align__(16) __nv_bfloat16 g_xh [(size_t)MROWS * HID];
__device__ __align__(16) unsigned char g_x8 [(size_t)MROWS * 2 * HID];
__device__ __align__(16) __nv_bfloat16 g_wgh[(size_t)INTER * HID];
__device__ __align__(16) unsigned char g_wg8[(size_t)INTER * 2 * HID];
__device__ __align__(16) __nv_bfloat16 g_wuh[(size_t)INTER * HID];
__device__ __align__(16) unsigned char g_wu8[(size_t)INTER * 2 * HID];
__device__ __align__(16) __nv_bfloat16 g_wdh[(size_t)HID * INTER];
__device__ __align__(16) unsigned char g_wd8[(size_t)HID * 2 * INTER];
__device__ __align__(16) float g_gate[(size_t)MROWS * INTER];
__device__ __align__(16) float g_up  [(size_t)MROWS * INTER];
__device__ __align__(16) __nv_bfloat16 g_ih [(size_t)MROWS * INTER];
__device__ __align__(16) unsigned char g_i8 [(size_t)MROWS * 2 * INTER];
__device__ float g_s[BATCH * INTER];

// ---------------------------------------------------------------------------
// PTX helpers (sm_80/sm_89-class only: cp.async + ldmatrix + mma.sync)
// ---------------------------------------------------------------------------
__device__ __forceinline__ uint32_t smem_u32(const void* p) {
    uint32_t a;
    asm("{ .reg .u64 t; cvta.to.shared.u64 t, %1; cvt.u32.u64 %0, t; }"
        : "=r"(a) : "l"(p));
    return a;
}

#define SWZ(o) ((o) ^ (((o) >> 3) & 0x70))

__device__ __forceinline__ void cp16(uint32_t s, const void* g) {
    asm volatile("cp.async.cg.shared.global [%0], [%1], 16;" :: "r"(s), "l"(g));
}
__device__ __forceinline__ void cp_commit() {
    asm volatile("cp.async.commit_group;" ::: "memory");
}
template <int N>
__device__ __forceinline__ void cp_wait() {
    asm volatile("cp.async.wait_group %0;" :: "n"(N) : "memory");
}

__device__ __forceinline__ void ldmx4(uint32_t* d, uint32_t addr) {
    asm volatile("ldmatrix.sync.aligned.m8n8.x4.shared.b16 {%0,%1,%2,%3}, [%4];"
                 : "=r"(d[0]), "=r"(d[1]), "=r"(d[2]), "=r"(d[3]) : "r"(addr));
}

__device__ __forceinline__ void mma_bf16(float* c, const uint32_t* a,
                                         const uint32_t* b) {
    asm volatile(
        "mma.sync.aligned.m16n8k16.row.col.f32.bf16.bf16.f32 "
        "{%0,%1,%2,%3}, {%4,%5,%6,%7}, {%8,%9}, {%0,%1,%2,%3};"
        : "+f"(c[0]), "+f"(c[1]), "+f"(c[2]), "+f"(c[3])
        : "r"(a[0]), "r"(a[1]), "r"(a[2]), "r"(a[3]), "r"(b[0]), "r"(b[1]));
}

// e4m3 x e4m3 -> f32, K=32: computes BOTH split cross terms in one op
__device__ __forceinline__ void mma_fp8(float* c, const uint32_t* a,
                                        const uint32_t* b) {
    asm volatile(
        "mma.sync.aligned.m16n8k32.row.col.f32.e4m3.e4m3.f32 "
        "{%0,%1,%2,%3}, {%4,%5,%6,%7}, {%8,%9}, {%0,%1,%2,%3};"
        : "+f"(c[0]), "+f"(c[1]), "+f"(c[2]), "+f"(c[3])
        : "r"(a[0]), "r"(a[1]), "r"(a[2]), "r"(a[3]), "r"(b[0]), "r"(b[1]));
}

// pack 4 floats into 4 e4m3 bytes (word j = fp8 pair (2j, 2j+1); byte order
// identical for A and B operands, so any intra-word swap self-cancels in MMA)
__device__ __forceinline__ uint32_t pack4_e4m3(float a, float b, float c, float d) {
    __nv_fp8x2_storage_t p0 =
        __nv_cvt_float2_to_fp8x2(make_float2(a, b), __NV_SATFINITE, __NV_E4M3);
    __nv_fp8x2_storage_t p1 =
        __nv_cvt_float2_to_fp8x2(make_float2(c, d), __NV_SATFINITE, __NV_E4M3);
    return (uint32_t)p0 | ((uint32_t)p1 << 16);
}

// ---------------------------------------------------------------------------
// GEMM: C[m,n] = sum_k A[m,k]*B[n,k]   (NT, K-major both)
// Main term: bf16 HMMA (Ah*Bh). Cross terms: one fp8 k32 HMMA per 16-k chunk
// with A8 = [e4m3(A) | e4m3(Alo*2^9)], B8 = [e4m3(Blo*2^15) | e4m3(Bh*2^6)].
// C = acc_h + acc_8 * 2^-15.
// CTA tile 128x128, BK=64, 3-stage cp.async, 512 thr (16 warps, 32x32 each).
// ---------------------------------------------------------------------------
#define STAGES 3
#define TILE_B 16384            // one 128-row x 128-byte tile (SW128 swizzled)
#define STAGE_B (4 * TILE_B)    // Ah(bf16), A8(fp8 packed), Bh(bf16), B8
#define GEMM_SMEM (STAGES * STAGE_B)    // 196608

__device__ __forceinline__ void load_stage(
    uint32_t stage_base,
    const __nv_bfloat16* __restrict__ Ah, const unsigned char* __restrict__ A8,
    const __nv_bfloat16* __restrict__ Bh, const unsigned char* __restrict__ B8,
    int K, int bm, int bn, int k0, int tid)
{
#pragma unroll
    for (int it = 0; it < 2; it++) {
        const int idx = tid + it * 512;          // 0..1023
        const int r = idx >> 3;                  // row 0..127
        const int c = idx & 7;                   // 16B chunk 0..7
        const uint32_t so = SWZ((uint32_t)(r * 128 + c * 16));
        const size_t gah = (size_t)(bm + r) * K + k0 + c * 8;       // bf16 elems
        const size_t ga8 = (size_t)(bm + r) * 2 * K + 2 * k0 + c * 16;  // bytes
        const size_t gbh = (size_t)(bn + r) * K + k0 + c * 8;
        const size_t gb8 = (size_t)(bn + r) * 2 * K + 2 * k0 + c * 16;
        cp16(stage_base + so,              Ah + gah);
        cp16(stage_base + TILE_B + so,     A8 + ga8);
        cp16(stage_base + 2 * TILE_B + so, Bh + gbh);
        cp16(stage_base + 3 * TILE_B + so, B8 + gb8);
    }
}

__global__ __launch_bounds__(512, 1) void gemm_hmma(
    const __nv_bfloat16* __restrict__ Ah, const unsigned char* __restrict__ A8,
    const __nv_bfloat16* __restrict__ Bh, const unsigned char* __restrict__ B8,
    float* __restrict__ C, int N, int K)
{
    extern __shared__ char smem[];
    const uint32_t sb = smem_u32(smem);
    const int tid  = threadIdx.x;
    const int wid  = tid >> 5;
    const int lane = tid & 31;
    const int bm = blockIdx.y * 128;
    const int bn = blockIdx.x * 128;
    const int KT = K >> 6;

    const int m0 = (wid & 3) * 32;
    const int n0 = (wid >> 2) * 32;

    float acch[2][4][4], acc8[2][4][4];
#pragma unroll
    for (int mt = 0; mt < 2; mt++)
#pragma unroll
        for (int nt = 0; nt < 4; nt++)
#pragma unroll
            for (int j = 0; j < 4; j++) { acch[mt][nt][j] = 0.f; acc8[mt][nt][j] = 0.f; }

    load_stage(sb, Ah, A8, Bh, B8, K, bm, bn, 0, tid);
    cp_commit();
    load_stage(sb + STAGE_B, Ah, A8, Bh, B8, K, bm, bn, 64, tid);
    cp_commit();

    const int arow = lane & 15;
    const int ak   = lane >> 4;
    const int brow = (lane & 7) + ((lane >> 4) & 1) * 8;
    const int bk   = (lane >> 3) & 1;

    for (int i = 0; i < KT; i++) {
        cp_wait<1>();
        __syncthreads();

        if (i + 2 < KT)
            load_stage(sb + ((i + 2) % STAGES) * STAGE_B, Ah, A8, Bh, B8,
                       K, bm, bn, (i + 2) * 64, tid);
        cp_commit();

        const uint32_t s0 = sb + (i % STAGES) * STAGE_B;
#pragma unroll
        for (int k = 0; k < 4; k++) {
            uint32_t ahf[2][4], a8f[2][4], bhf[4][2], b8f[4][2];
#pragma unroll
            for (int mt = 0; mt < 2; mt++) {
                const uint32_t off =
                    SWZ((uint32_t)((m0 + mt * 16 + arow) * 128 + (2 * k + ak) * 16));
                ldmx4(ahf[mt], s0 + off);
                ldmx4(a8f[mt], s0 + TILE_B + off);
            }
#pragma unroll
            for (int np = 0; np < 2; np++) {
                const uint32_t off =
                    SWZ((uint32_t)((n0 + np * 16 + brow) * 128 + (2 * k + bk) * 16));
                uint32_t q[4];
                ldmx4(q, s0 + 2 * TILE_B + off);
                bhf[2 * np][0] = q[0]; bhf[2 * np][1] = q[1];
                bhf[2 * np + 1][0] = q[2]; bhf[2 * np + 1][1] = q[3];
                ldmx4(q, s0 + 3 * TILE_B + off);
                b8f[2 * np][0] = q[0]; b8f[2 * np][1] = q[1];
                b8f[2 * np + 1][0] = q[2]; b8f[2 * np + 1][1] = q[3];
            }
#pragma unroll
            for (int mt = 0; mt < 2; mt++)
#pragma unroll
                for (int nt = 0; nt < 4; nt++) {
                    mma_bf16(acch[mt][nt], ahf[mt], bhf[nt]);
                    mma_fp8 (acc8[mt][nt], a8f[mt], b8f[nt]);
                }
        }
    }

#pragma unroll
    for (int mt = 0; mt < 2; mt++) {
        const int row = bm + m0 + mt * 16 + (lane >> 2);
#pragma unroll
        for (int nt = 0; nt < 4; nt++) {
            const int col = bn + n0 + nt * 8 + (lane & 3) * 2;
            float2* p0 = (float2*)&C[(size_t)row * N + col];
            float2* p1 = (float2*)&C[(size_t)(row + 8) * N + col];
            *p0 = make_float2(acch[mt][nt][0] + acc8[mt][nt][0] * INV_CROSS,
                              acch[mt][nt][1] + acc8[mt][nt][1] * INV_CROSS);
            *p1 = make_float2(acch[mt][nt][2] + acc8[mt][nt][2] * INV_CROSS,
                              acch[mt][nt][3] + acc8[mt][nt][3] * INV_CROSS);
        }
    }
}

// ---------------------------------------------------------------------------
// Splits. A-type (x / inter): hi8 = e4m3(v), lo8 = e4m3(lo*2^9); packed [hi|lo].
// B-type (weights): hi8 = e4m3(v*2^6), lo8 = e4m3(lo*2^15); packed [lo|hi].
// ---------------------------------------------------------------------------
__global__ __launch_bounds__(256) void split_A_kernel(
    const float* __restrict__ in, __nv_bfloat16* __restrict__ hi,
    unsigned char* __restrict__ p8, int n4, int K)
{
    const int i = blockIdx.x * 256 + threadIdx.x;
    if (i >= n4) return;
    const int idx4 = i * 4;
    const float4 v = ((const float4*)in)[i];
    __nv_bfloat16 h0 = __float2bfloat16(v.x), h1 = __float2bfloat16(v.y);
    __nv_bfloat16 h2 = __float2bfloat16(v.z), h3 = __float2bfloat16(v.w);
    __nv_bfloat162* hp = (__nv_bfloat162*)(hi + idx4);
    hp[0] = __nv_bfloat162(h0, h1);
    hp[1] = __nv_bfloat162(h2, h3);
    const float l0 = v.x - __bfloat162float(h0), l1 = v.y - __bfloat162float(h1);
    const float l2 = v.z - __bfloat162float(h2), l3 = v.w - __bfloat162float(h3);
    const int row = idx4 / K;
    const int k = idx4 - row * K;
    const size_t base = (size_t)row * 2 * K + 32 * (k >> 4) + (k & 15);
    *(uint32_t*)(p8 + base)      = pack4_e4m3(v.x, v.y, v.z, v.w);
    *(uint32_t*)(p8 + base + 16) = pack4_e4m3(l0 * S_LO_A, l1 * S_LO_A,
                                              l2 * S_LO_A, l3 * S_LO_A);
}

__global__ __launch_bounds__(256) void split_B_kernel(
    const float* __restrict__ in, __nv_bfloat16* __restrict__ hi,
    unsigned char* __restrict__ p8, int n4, int K)
{
    const int i = blockIdx.x * 256 + threadIdx.x;
    if (i >= n4) return;
    const int idx4 = i * 4;
    const float4 v = ((const float4*)in)[i];
    __nv_bfloat16 h0 = __float2bfloat16(v.x), h1 = __float2bfloat16(v.y);
    __nv_bfloat16 h2 = __float2bfloat16(v.z), h3 = __float2bfloat16(v.w);
    __nv_bfloat162* hp = (__nv_bfloat162*)(hi + idx4);
    hp[0] = __nv_bfloat162(h0, h1);
    hp[1] = __nv_bfloat162(h2, h3);
    const float l0 = v.x - __bfloat162float(h0), l1 = v.y - __bfloat162float(h1);
    const float l2 = v.z - __bfloat162float(h2), l3 = v.w - __bfloat162float(h3);
    const int row = idx4 / K;
    const int k = idx4 - row * K;
    const size_t base = (size_t)row * 2 * K + 32 * (k >> 4) + (k & 15);
    *(uint32_t*)(p8 + base)      = pack4_e4m3(l0 * S_LO_B, l1 * S_LO_B,
                                              l2 * S_LO_B, l3 * S_LO_B);
    *(uint32_t*)(p8 + base + 16) = pack4_e4m3(v.x * S_HI_B, v.y * S_HI_B,
                                              v.z * S_HI_B, v.w * S_HI_B);
}

// ---------------------------------------------------------------------------
__global__ void zero_s_kernel()
{
    int i = blockIdx.x * 256 + threadIdx.x;
    if (i < BATCH * INTER) g_s[i] = 0.f;
}

// ---------------------------------------------------------------------------
// SwiGLU: inter = silu(gate)*up -> bf16-hi + packed fp8 (A-type); s += inter^2
// ---------------------------------------------------------------------------
__global__ __launch_bounds__(256) void swiglu_kernel()
{
    const int b = blockIdx.z;
    const int i4 = (blockIdx.x * 256 + threadIdx.x) * 4;
    const int s0 = blockIdx.y * 128;
    if (i4 >= INTER) return;

    const size_t pbase = 32 * (size_t)(i4 >> 4) + (i4 & 15);
    float a0 = 0.f, a1 = 0.f, a2 = 0.f, a3 = 0.f;
    for (int s = s0; s < s0 + 128; s++) {
        const size_t row = (size_t)b * SEQ + s;
        const size_t idx = row * INTER + i4;
        const float4 g = *(const float4*)(g_gate + idx);
        const float4 u = *(const float4*)(g_up + idx);
        const float v0 = g.x / (1.f + expf(-g.x)) * u.x;
        const float v1 = g.y / (1.f + expf(-g.y)) * u.y;
        const float v2 = g.z / (1.f + expf(-g.z)) * u.z;
        const float v3 = g.w / (1.f + expf(-g.w)) * u.w;
        a0 += v0 * v0; a1 += v1 * v1; a2 += v2 * v2; a3 += v3 * v3;
        __nv_bfloat16 h0 = __float2bfloat16(v0), h1 = __float2bfloat16(v1);
        __nv_bfloat16 h2 = __float2bfloat16(v2), h3 = __float2bfloat16(v3);
        __nv_bfloat162* hp = (__nv_bfloat162*)(g_ih + idx);
        hp[0] = __nv_bfloat162(h0, h1);
        hp[1] = __nv_bfloat162(h2, h3);
        const float l0 = v0 - __bfloat162float(h0), l1 = v1 - __bfloat162float(h1);
        const float l2 = v2 - __bfloat162float(h2), l3 = v3 - __bfloat162float(h3);
        unsigned char* p = g_i8 + row * 2 * INTER + pbase;
        *(uint32_t*)(p)      = pack4_e4m3(v0, v1, v2, v3);
        *(uint32_t*)(p + 16) = pack4_e4m3(l0 * S_LO_A, l1 * S_LO_A,
                                          l2 * S_LO_A, l3 * S_LO_A);
    }
    atomicAdd(&g_s[b * INTER + i4 + 0], a0);
    atomicAdd(&g_s[b * INTER + i4 + 1], a1);
    atomicAdd(&g_s[b * INTER + i4 + 2], a2);
    atomicAdd(&g_s[b * INTER + i4 + 3], a3);
}

// ---------------------------------------------------------------------------
__global__ __launch_bounds__(256) void impacts_kernel(
    const float* __restrict__ w_up, float* __restrict__ out_imp)
{
    __shared__ float red[256];
    const int i = blockIdx.x;
    float acc = 0.f;
    for (int h = threadIdx.x; h < HID; h += 256) {
        const float w = w_up[(size_t)i * HID + h];
        acc += w * w;
    }
    red[threadIdx.x] = acc;
    __syncthreads();
    for (int off = 128; off > 0; off >>= 1) {
        if (threadIdx.x < off) red[threadIdx.x] += red[threadIdx.x + off];
        __syncthreads();
    }
    if (threadIdx.x == 0) {
        const float rs = red[0];
#pragma unroll
        for (int b = 0; b < BATCH; b++)
            out_imp[b * INTER + i] = sqrtf(g_s[b * INTER + i] * rs);
    }
}

// ---------------------------------------------------------------------------
extern "C" void kernel_launch(void* const* d_in, const int* in_sizes, int n_in,
                              void* d_out, int out_size)
{
    const float* x      = (const float*)d_in[0];
    const float* w_gate = (const float*)d_in[1];
    const float* w_up   = (const float*)d_in[2];
    const float* w_down = (const float*)d_in[3];
    float* out = (float*)d_out;

    __nv_bfloat16 *xh, *wgh, *wuh, *wdh, *ih;
    unsigned char *x8, *wg8, *wu8, *wd8, *i8;
    float *gate, *up;
    cudaGetSymbolAddress((void**)&xh,  g_xh);
    cudaGetSymbolAddress((void**)&x8,  g_x8);
    cudaGetSymbolAddress((void**)&wgh, g_wgh);
    cudaGetSymbolAddress((void**)&wg8, g_wg8);
    cudaGetSymbolAddress((void**)&wuh, g_wuh);
    cudaGetSymbolAddress((void**)&wu8, g_wu8);
    cudaGetSymbolAddress((void**)&wdh, g_wdh);
    cudaGetSymbolAddress((void**)&wd8, g_wd8);
    cudaGetSymbolAddress((void**)&ih,  g_ih);
    cudaGetSymbolAddress((void**)&i8,  g_i8);
    cudaGetSymbolAddress((void**)&gate, g_gate);
    cudaGetSymbolAddress((void**)&up,   g_up);

    cudaFuncSetAttribute(gemm_hmma,
                         cudaFuncAttributeMaxDynamicSharedMemorySize, GEMM_SMEM);

    zero_s_kernel<<<(BATCH * INTER + 255) / 256, 256>>>();

    {
        const int nx4 = MROWS * HID / 4;
        split_A_kernel<<<(nx4 + 255) / 256, 256>>>(x, xh, x8, nx4, HID);
        const int nw4 = INTER * HID / 4;
        split_B_kernel<<<(nw4 + 255) / 256, 256>>>(w_gate, wgh, wg8, nw4, HID);
        split_B_kernel<<<(nw4 + 255) / 256, 256>>>(w_up, wuh, wu8, nw4, HID);
        split_B_kernel<<<(nw4 + 255) / 256, 256>>>(w_down, wdh, wd8, nw4, INTER);
    }

    // gate = x @ w_gate^T ; up = x @ w_up^T   (M=8192, N=5504, K=2048)
    {
        dim3 grid(INTER / 128, MROWS / 128);
        gemm_hmma<<<grid, 512, GEMM_SMEM>>>(xh, x8, wgh, wg8, gate, INTER, HID);
        gemm_hmma<<<grid, 512, GEMM_SMEM>>>(xh, x8, wuh, wu8, up, INTER, HID);
    }

    // inter = silu(gate)*up ; s accumulation
    {
        dim3 grid((INTER / 4 + 255) / 256, 16, BATCH);
        swiglu_kernel<<<grid, 256>>>();
    }

    // out = inter @ w_down^T  (M=8192, N=2048, K=5504)
    {
        dim3 grid(HID / 128, MROWS / 128);
        gemm_hmma<<<grid, 512, GEMM_SMEM>>>(ih, i8, wdh, wd8, out, HID, INTER);
    }

    impacts_kernel<<<INTER, 256>>>(w_up, out + (size_t)MROWS * HID);
}

// round 6
// speedup vs baseline: 3.3473x; 3.3473x over previous
#include <cuda_runtime.h>
#include <cuda_fp16.h>
#include <math.h>
#include <stdint.h>

#define BATCH 4
#define SEQ   2048
#define HID   2048
#define INTER 5504
#define MROWS (BATCH * SEQ)            // 8192

// ---------------------------------------------------------------------------
// Scratch (device globals; no allocation allowed)
// ---------------------------------------------------------------------------
__device__ __align__(16) __half g_xh [(size_t)MROWS * HID];
__device__ __align__(16) __half g_wgh[(size_t)INTER * HID];
__device__ __align__(16) __half g_wuh[(size_t)INTER * HID];
__device__ __align__(16) __half g_wdh[(size_t)HID * INTER];
__device__ __align__(16) float  g_gate[(size_t)MROWS * INTER];
__device__ __align__(16) float  g_up  [(size_t)MROWS * INTER];
__device__ __align__(16) __half g_if [(size_t)MROWS * INTER];
__device__ float g_s[BATCH * INTER];

// ---------------------------------------------------------------------------
// PTX helpers (sm_80-class only: cp.async + ldmatrix + mma.sync)
// ---------------------------------------------------------------------------
__device__ __forceinline__ uint32_t smem_u32(const void* p) {
    uint32_t a;
    asm("{ .reg .u64 t; cvta.to.shared.u64 t, %1; cvt.u32.u64 %0, t; }"
        : "=r"(a) : "l"(p));
    return a;
}

#define SWZ(o) ((o) ^ (((o) >> 3) & 0x70))

__device__ __forceinline__ void cp16(uint32_t s, const void* g) {
    asm volatile("cp.async.cg.shared.global [%0], [%1], 16;" :: "r"(s), "l"(g));
}
__device__ __forceinline__ void cp_commit() {
    asm volatile("cp.async.commit_group;" ::: "memory");
}
template <int N>
__device__ __forceinline__ void cp_wait() {
    asm volatile("cp.async.wait_group %0;" :: "n"(N) : "memory");
}

__device__ __forceinline__ void ldmx4(uint32_t* d, uint32_t addr) {
    asm volatile("ldmatrix.sync.aligned.m8n8.x4.shared.b16 {%0,%1,%2,%3}, [%4];"
                 : "=r"(d[0]), "=r"(d[1]), "=r"(d[2]), "=r"(d[3]) : "r"(addr));
}

__device__ __forceinline__ void mma_fp16(float* c, const uint32_t* a,
                                         const uint32_t* b) {
    asm volatile(
        "mma.sync.aligned.m16n8k16.row.col.f32.f16.f16.f32 "
        "{%0,%1,%2,%3}, {%4,%5,%6,%7}, {%8,%9}, {%0,%1,%2,%3};"
        : "+f"(c[0]), "+f"(c[1]), "+f"(c[2]), "+f"(c[3])
        : "r"(a[0]), "r"(a[1]), "r"(a[2]), "r"(a[3]), "r"(b[0]), "r"(b[1]));
}

// ---------------------------------------------------------------------------
// fp16 HMMA GEMM: C[m,n] = sum_k A[m,k]*B[n,k]  (NT, K-major both, fp16 in,
// fp32 accum). CTA tile 128x128, BK=64, 3-stage cp.async pipeline, 256 thr
// (8 warps, warp tile 32x64), 2 CTAs/SM.
// Requires M%128==0, N%128==0, K%64==0, K/64 >= 3.
// ---------------------------------------------------------------------------
#define STAGES 3
#define TILE_B 16384            // one 128-row x 128-byte tile (SW128 swizzled)
#define STAGE_B (2 * TILE_B)    // A, B
#define GEMM_SMEM (STAGES * STAGE_B)    // 98304

__device__ __forceinline__ void load_stage(
    uint32_t stage_base,
    const __half* __restrict__ A, const __half* __restrict__ B,
    int K, int bm, int bn, int k0, int tid)
{
#pragma unroll
    for (int it = 0; it < 4; it++) {
        const int idx = tid + it * 256;          // 0..1023
        const int r = idx >> 3;                  // row 0..127
        const int c = idx & 7;                   // 16B chunk 0..7
        const uint32_t so = SWZ((uint32_t)(r * 128 + c * 16));
        cp16(stage_base + so,          A + (size_t)(bm + r) * K + k0 + c * 8);
        cp16(stage_base + TILE_B + so, B + (size_t)(bn + r) * K + k0 + c * 8);
    }
}

__global__ __launch_bounds__(256, 2) void gemm_fp16(
    const __half* __restrict__ A, const __half* __restrict__ B,
    float* __restrict__ C, int N, int K)
{
    extern __shared__ char smem[];
    const uint32_t sb = smem_u32(smem);
    const int tid  = threadIdx.x;
    const int wid  = tid >> 5;
    const int lane = tid & 31;
    const int bm = blockIdx.y * 128;
    const int bn = blockIdx.x * 128;
    const int KT = K >> 6;

    const int m0 = (wid & 3) * 32;     // warp rows: 4 warps down
    const int n0 = (wid >> 2) * 64;    // warp cols: 2 warps across

    float acc[2][8][4];
#pragma unroll
    for (int mt = 0; mt < 2; mt++)
#pragma unroll
        for (int nt = 0; nt < 8; nt++)
#pragma unroll
            for (int j = 0; j < 4; j++) acc[mt][nt][j] = 0.f;

    load_stage(sb, A, B, K, bm, bn, 0, tid);
    cp_commit();
    load_stage(sb + STAGE_B, A, B, K, bm, bn, 64, tid);
    cp_commit();

    const int arow = lane & 15;
    const int ak   = lane >> 4;
    const int brow = (lane & 7) + ((lane >> 4) & 1) * 8;
    const int bk   = (lane >> 3) & 1;

    for (int i = 0; i < KT; i++) {
        cp_wait<1>();
        __syncthreads();

        if (i + 2 < KT)
            load_stage(sb + ((i + 2) % STAGES) * STAGE_B, A, B,
                       K, bm, bn, (i + 2) * 64, tid);
        cp_commit();   // uniform group accounting (possibly empty)

        const uint32_t s0 = sb + (i % STAGES) * STAGE_B;
#pragma unroll
        for (int k = 0; k < 4; k++) {
            uint32_t af[2][4], bf[8][2];
#pragma unroll
            for (int mt = 0; mt < 2; mt++) {
                const uint32_t off =
                    SWZ((uint32_t)((m0 + mt * 16 + arow) * 128 + (2 * k + ak) * 16));
                ldmx4(af[mt], s0 + off);
            }
#pragma unroll
            for (int np = 0; np < 4; np++) {
                const uint32_t off =
                    SWZ((uint32_t)((n0 + np * 16 + brow) * 128 + (2 * k + bk) * 16));
                uint32_t q[4];
                ldmx4(q, s0 + TILE_B + off);
                bf[2 * np][0] = q[0]; bf[2 * np][1] = q[1];
                bf[2 * np + 1][0] = q[2]; bf[2 * np + 1][1] = q[3];
            }
#pragma unroll
            for (int mt = 0; mt < 2; mt++)
#pragma unroll
                for (int nt = 0; nt < 8; nt++)
                    mma_fp16(acc[mt][nt], af[mt], bf[nt]);
        }
    }

#pragma unroll
    for (int mt = 0; mt < 2; mt++) {
        const int row = bm + m0 + mt * 16 + (lane >> 2);
#pragma unroll
        for (int nt = 0; nt < 8; nt++) {
            const int col = bn + n0 + nt * 8 + (lane & 3) * 2;
            float2* p0 = (float2*)&C[(size_t)row * N + col];
            float2* p1 = (float2*)&C[(size_t)(row + 8) * N + col];
            *p0 = make_float2(acc[mt][nt][0], acc[mt][nt][1]);
            *p1 = make_float2(acc[mt][nt][2], acc[mt][nt][3]);
        }
    }
}

// ---------------------------------------------------------------------------
// fp32 -> fp16 convert
// ---------------------------------------------------------------------------
__global__ __launch_bounds__(256) void cvt_fp16_kernel(
    const float* __restrict__ in, __half* __restrict__ out, int n4)
{
    const int i = blockIdx.x * 256 + threadIdx.x;
    if (i >= n4) return;
    const float4 v = ((const float4*)in)[i];
    __half2* p = (__half2*)(out + (size_t)i * 4);
    p[0] = __floats2half2_rn(v.x, v.y);
    p[1] = __floats2half2_rn(v.z, v.w);
}

// ---------------------------------------------------------------------------
__global__ void zero_s_kernel()
{
    int i = blockIdx.x * 256 + threadIdx.x;
    if (i < BATCH * INTER) g_s[i] = 0.f;
}

// ---------------------------------------------------------------------------
// SwiGLU: inter = silu(gate)*up -> fp16 ; s += sum_seq inter^2 (fp32)
// ---------------------------------------------------------------------------
__global__ __launch_bounds__(256) void swiglu_kernel()
{
    const int b = blockIdx.z;
    const int i4 = (blockIdx.x * 256 + threadIdx.x) * 4;
    const int s0 = blockIdx.y * 128;
    if (i4 >= INTER) return;

    float a0 = 0.f, a1 = 0.f, a2 = 0.f, a3 = 0.f;
    for (int s = s0; s < s0 + 128; s++) {
        const size_t idx = ((size_t)b * SEQ + s) * INTER + i4;
        const float4 g = *(const float4*)(g_gate + idx);
        const float4 u = *(const float4*)(g_up + idx);
        const float v0 = g.x / (1.f + expf(-g.x)) * u.x;
        const float v1 = g.y / (1.f + expf(-g.y)) * u.y;
        const float v2 = g.z / (1.f + expf(-g.z)) * u.z;
        const float v3 = g.w / (1.f + expf(-g.w)) * u.w;
        a0 += v0 * v0; a1 += v1 * v1; a2 += v2 * v2; a3 += v3 * v3;
        __half2* p = (__half2*)(g_if + idx);
        p[0] = __floats2half2_rn(v0, v1);
        p[1] = __floats2half2_rn(v2, v3);
    }
    atomicAdd(&g_s[b * INTER + i4 + 0], a0);
    atomicAdd(&g_s[b * INTER + i4 + 1], a1);
    atomicAdd(&g_s[b * INTER + i4 + 2], a2);
    atomicAdd(&g_s[b * INTER + i4 + 3], a3);
}

// ---------------------------------------------------------------------------
__global__ __launch_bounds__(256) void impacts_kernel(
    const float* __restrict__ w_up, float* __restrict__ out_imp)
{
    __shared__ float red[256];
    const int i = blockIdx.x;
    float acc = 0.f;
    for (int h = threadIdx.x; h < HID; h += 256) {
        const float w = w_up[(size_t)i * HID + h];
        acc += w * w;
    }
    red[threadIdx.x] = acc;
    __syncthreads();
    for (int off = 128; off > 0; off >>= 1) {
        if (threadIdx.x < off) red[threadIdx.x] += red[threadIdx.x + off];
        __syncthreads();
    }
    if (threadIdx.x == 0) {
        const float rs = red[0];
#pragma unroll
        for (int b = 0; b < BATCH; b++)
            out_imp[b * INTER + i] = sqrtf(g_s[b * INTER + i] * rs);
    }
}

// ---------------------------------------------------------------------------
extern "C" void kernel_launch(void* const* d_in, const int* in_sizes, int n_in,
                              void* d_out, int out_size)
{
    const float* x      = (const float*)d_in[0];
    const float* w_gate = (const float*)d_in[1];
    const float* w_up   = (const float*)d_in[2];
    const float* w_down = (const float*)d_in[3];
    float* out = (float*)d_out;

    __half *xh, *wgh, *wuh, *wdh, *ifp;
    float *gate, *up;
    cudaGetSymbolAddress((void**)&xh,  g_xh);
    cudaGetSymbolAddress((void**)&wgh, g_wgh);
    cudaGetSymbolAddress((void**)&wuh, g_wuh);
    cudaGetSymbolAddress((void**)&wdh, g_wdh);
    cudaGetSymbolAddress((void**)&ifp, g_if);
    cudaGetSymbolAddress((void**)&gate, g_gate);
    cudaGetSymbolAddress((void**)&up,   g_up);

    cudaFuncSetAttribute(gemm_fp16,
                         cudaFuncAttributeMaxDynamicSharedMemorySize, GEMM_SMEM);

    zero_s_kernel<<<(BATCH * INTER + 255) / 256, 256>>>();

    {
        const int nx4 = MROWS * HID / 4;
        cvt_fp16_kernel<<<(nx4 + 255) / 256, 256>>>(x, xh, nx4);
        const int nw4 = INTER * HID / 4;
        cvt_fp16_kernel<<<(nw4 + 255) / 256, 256>>>(w_gate, wgh, nw4);
        cvt_fp16_kernel<<<(nw4 + 255) / 256, 256>>>(w_up, wuh, nw4);
        cvt_fp16_kernel<<<(nw4 + 255) / 256, 256>>>(w_down, wdh, nw4);
    }

    // gate = x @ w_gate^T ; up = x @ w_up^T   (M=8192, N=5504, K=2048)
    {
        dim3 grid(INTER / 128, MROWS / 128);
        gemm_fp16<<<grid, 256, GEMM_SMEM>>>(xh, wgh, gate, INTER, HID);
        gemm_fp16<<<grid, 256, GEMM_SMEM>>>(xh, wuh, up, INTER, HID);
    }

    // inter = silu(gate)*up -> fp16 ; s accumulation
    {
        dim3 grid((INTER / 4 + 255) / 256, 16, BATCH);
        swiglu_kernel<<<grid, 256>>>();
    }

    // out = inter @ w_down^T  (M=8192, N=2048, K=5504)
    {
        dim3 grid(HID / 128, MROWS / 128);
        gemm_fp16<<<grid, 256, GEMM_SMEM>>>(ifp, wdh, out, HID, INTER);
    }

    impacts_kernel<<<INTER, 256>>>(w_up, out + (size_t)MROWS * HID);
}

// round 7
// speedup vs baseline: 3.5576x; 1.0628x over previous
#include <cuda_runtime.h>
#include <cuda_fp16.h>
#include <math.h>
#include <stdint.h>

#define BATCH 4
#define SEQ   2048
#define HID   2048
#define INTER 5504
#define MROWS (BATCH * SEQ)            // 8192

// ---------------------------------------------------------------------------
// Scratch (device globals; no allocation allowed)
// ---------------------------------------------------------------------------
__device__ __align__(16) __half g_xh [(size_t)MROWS * HID];
__device__ __align__(16) __half g_wgh[(size_t)INTER * HID];
__device__ __align__(16) __half g_wuh[(size_t)INTER * HID];
__device__ __align__(16) __half g_wdh[(size_t)HID * INTER];
__device__ __align__(16) __half g_if [(size_t)MROWS * INTER];
__device__ float g_s[BATCH * INTER];

// ---------------------------------------------------------------------------
// PTX helpers (sm_80-class only: cp.async + ldmatrix + mma.sync)
// ---------------------------------------------------------------------------
__device__ __forceinline__ uint32_t smem_u32(const void* p) {
    uint32_t a;
    asm("{ .reg .u64 t; cvta.to.shared.u64 t, %1; cvt.u32.u64 %0, t; }"
        : "=r"(a) : "l"(p));
    return a;
}

#define SWZ(o) ((o) ^ (((o) >> 3) & 0x70))

__device__ __forceinline__ void cp16(uint32_t s, const void* g) {
    asm volatile("cp.async.cg.shared.global [%0], [%1], 16;" :: "r"(s), "l"(g));
}
__device__ __forceinline__ void cp_commit() {
    asm volatile("cp.async.commit_group;" ::: "memory");
}
template <int N>
__device__ __forceinline__ void cp_wait() {
    asm volatile("cp.async.wait_group %0;" :: "n"(N) : "memory");
}

__device__ __forceinline__ void ldmx4(uint32_t* d, uint32_t addr) {
    asm volatile("ldmatrix.sync.aligned.m8n8.x4.shared.b16 {%0,%1,%2,%3}, [%4];"
                 : "=r"(d[0]), "=r"(d[1]), "=r"(d[2]), "=r"(d[3]) : "r"(addr));
}

__device__ __forceinline__ void mma_fp16(float* c, const uint32_t* a,
                                         const uint32_t* b) {
    asm volatile(
        "mma.sync.aligned.m16n8k16.row.col.f32.f16.f16.f32 "
        "{%0,%1,%2,%3}, {%4,%5,%6,%7}, {%8,%9}, {%0,%1,%2,%3};"
        : "+f"(c[0]), "+f"(c[1]), "+f"(c[2]), "+f"(c[3])
        : "r"(a[0]), "r"(a[1]), "r"(a[2]), "r"(a[3]), "r"(b[0]), "r"(b[1]));
}

#define TILE_B 16384            // one 128-row x 128-byte tile (SW128 swizzled)

// ===========================================================================
// Fused gate+up GEMM + SwiGLU epilogue.
// inter[m, n] = silu(x@wg^T) * (x@wu^T), written fp16 to g_if.
// s[b, n] += sum over tile rows of inter^2  (warp-reduced atomics).
// CTA tile 128x128, BK=64, 3-stage pipeline (A, Bg, Bu per stage = 48KB),
// 256 thr (8 warps, warp tile 32x64), 1 CTA/SM.
// ===========================================================================
#define FSTAGE_B (3 * TILE_B)
#define FUSED_SMEM (3 * FSTAGE_B)       // 147456

__device__ __forceinline__ void load_stage_f(
    uint32_t stage_base,
    const __half* __restrict__ A, const __half* __restrict__ Bg,
    const __half* __restrict__ Bu, int bm, int bn, int k0, int tid)
{
#pragma unroll
    for (int it = 0; it < 4; it++) {
        const int idx = tid + it * 256;          // 0..1023
        const int r = idx >> 3;
        const int c = idx & 7;
        const uint32_t so = SWZ((uint32_t)(r * 128 + c * 16));
        cp16(stage_base + so,              A  + (size_t)(bm + r) * HID + k0 + c * 8);
        cp16(stage_base + TILE_B + so,     Bg + (size_t)(bn + r) * HID + k0 + c * 8);
        cp16(stage_base + 2 * TILE_B + so, Bu + (size_t)(bn + r) * HID + k0 + c * 8);
    }
}

__global__ __launch_bounds__(256, 1) void gateup_fused(
    const __half* __restrict__ A, const __half* __restrict__ Bg,
    const __half* __restrict__ Bu)
{
    extern __shared__ char smem[];
    const uint32_t sb = smem_u32(smem);
    const int tid  = threadIdx.x;
    const int wid  = tid >> 5;
    const int lane = tid & 31;
    const int bm = blockIdx.y * 128;
    const int bn = blockIdx.x * 128;
    const int KT = HID >> 6;               // 32

    const int m0 = (wid & 3) * 32;
    const int n0 = (wid >> 2) * 64;

    float accg[2][8][4], accu[2][8][4];
#pragma unroll
    for (int mt = 0; mt < 2; mt++)
#pragma unroll
        for (int nt = 0; nt < 8; nt++)
#pragma unroll
            for (int j = 0; j < 4; j++) { accg[mt][nt][j] = 0.f; accu[mt][nt][j] = 0.f; }

    load_stage_f(sb, A, Bg, Bu, bm, bn, 0, tid);
    cp_commit();
    load_stage_f(sb + FSTAGE_B, A, Bg, Bu, bm, bn, 64, tid);
    cp_commit();

    const int arow = lane & 15;
    const int ak   = lane >> 4;
    const int brow = (lane & 7) + ((lane >> 4) & 1) * 8;
    const int bk   = (lane >> 3) & 1;

    for (int i = 0; i < KT; i++) {
        cp_wait<1>();
        __syncthreads();

        if (i + 2 < KT)
            load_stage_f(sb + ((i + 2) % 3) * FSTAGE_B, A, Bg, Bu,
                         bm, bn, (i + 2) * 64, tid);
        cp_commit();

        const uint32_t s0 = sb + (i % 3) * FSTAGE_B;
#pragma unroll
        for (int k = 0; k < 4; k++) {
            uint32_t af[2][4], bf[8][2];
#pragma unroll
            for (int mt = 0; mt < 2; mt++) {
                const uint32_t off =
                    SWZ((uint32_t)((m0 + mt * 16 + arow) * 128 + (2 * k + ak) * 16));
                ldmx4(af[mt], s0 + off);
            }
            const uint32_t boff[4] = {
                SWZ((uint32_t)((n0 + 0 * 16 + brow) * 128 + (2 * k + bk) * 16)),
                SWZ((uint32_t)((n0 + 1 * 16 + brow) * 128 + (2 * k + bk) * 16)),
                SWZ((uint32_t)((n0 + 2 * 16 + brow) * 128 + (2 * k + bk) * 16)),
                SWZ((uint32_t)((n0 + 3 * 16 + brow) * 128 + (2 * k + bk) * 16))};
            // gate B
#pragma unroll
            for (int np = 0; np < 4; np++) {
                uint32_t q[4];
                ldmx4(q, s0 + TILE_B + boff[np]);
                bf[2 * np][0] = q[0]; bf[2 * np][1] = q[1];
                bf[2 * np + 1][0] = q[2]; bf[2 * np + 1][1] = q[3];
            }
#pragma unroll
            for (int mt = 0; mt < 2; mt++)
#pragma unroll
                for (int nt = 0; nt < 8; nt++)
                    mma_fp16(accg[mt][nt], af[mt], bf[nt]);
            // up B
#pragma unroll
            for (int np = 0; np < 4; np++) {
                uint32_t q[4];
                ldmx4(q, s0 + 2 * TILE_B + boff[np]);
                bf[2 * np][0] = q[0]; bf[2 * np][1] = q[1];
                bf[2 * np + 1][0] = q[2]; bf[2 * np + 1][1] = q[3];
            }
#pragma unroll
            for (int mt = 0; mt < 2; mt++)
#pragma unroll
                for (int nt = 0; nt < 8; nt++)
                    mma_fp16(accu[mt][nt], af[mt], bf[nt]);
        }
    }

    // ---- epilogue: inter = silu(g)*u -> fp16 ; s += sum_rows inter^2 ----
    const int b = bm >> 11;                         // SEQ = 2048 rows per batch
#pragma unroll
    for (int nt = 0; nt < 8; nt++) {
        const int col = bn + n0 + nt * 8 + (lane & 3) * 2;
        float sq0 = 0.f, sq1 = 0.f;
#pragma unroll
        for (int mt = 0; mt < 2; mt++) {
            const int row = bm + m0 + mt * 16 + (lane >> 2);
            const float* gg = accg[mt][nt];
            const float* uu = accu[mt][nt];
            const float v0 = gg[0] / (1.f + expf(-gg[0])) * uu[0];
            const float v1 = gg[1] / (1.f + expf(-gg[1])) * uu[1];
            const float v2 = gg[2] / (1.f + expf(-gg[2])) * uu[2];
            const float v3 = gg[3] / (1.f + expf(-gg[3])) * uu[3];
            *(__half2*)&g_if[(size_t)row * INTER + col]       = __floats2half2_rn(v0, v1);
            *(__half2*)&g_if[(size_t)(row + 8) * INTER + col] = __floats2half2_rn(v2, v3);
            sq0 += v0 * v0 + v2 * v2;
            sq1 += v1 * v1 + v3 * v3;
        }
        // reduce over the 8 row-lanes (bits 2..4 of lane)
#pragma unroll
        for (int off = 4; off <= 16; off <<= 1) {
            sq0 += __shfl_xor_sync(0xffffffffu, sq0, off);
            sq1 += __shfl_xor_sync(0xffffffffu, sq1, off);
        }
        if ((lane >> 2) == 0) {
            atomicAdd(&g_s[b * INTER + col],     sq0);
            atomicAdd(&g_s[b * INTER + col + 1], sq1);
        }
    }
}

// ===========================================================================
// Plain fp16 GEMM (down projection): C = A @ B^T, fp32 out.
// CTA 128x128, BK=64, 3 stages, 256 thr, 2 CTAs/SM.
// ===========================================================================
#define STAGE_B (2 * TILE_B)
#define GEMM_SMEM (3 * STAGE_B)         // 98304

__device__ __forceinline__ void load_stage(
    uint32_t stage_base,
    const __half* __restrict__ A, const __half* __restrict__ B,
    int K, int bm, int bn, int k0, int tid)
{
#pragma unroll
    for (int it = 0; it < 4; it++) {
        const int idx = tid + it * 256;
        const int r = idx >> 3;
        const int c = idx & 7;
        const uint32_t so = SWZ((uint32_t)(r * 128 + c * 16));
        cp16(stage_base + so,          A + (size_t)(bm + r) * K + k0 + c * 8);
        cp16(stage_base + TILE_B + so, B + (size_t)(bn + r) * K + k0 + c * 8);
    }
}

__global__ __launch_bounds__(256, 2) void gemm_fp16(
    const __half* __restrict__ A, const __half* __restrict__ B,
    float* __restrict__ C, int N, int K)
{
    extern __shared__ char smem[];
    const uint32_t sb = smem_u32(smem);
    const int tid  = threadIdx.x;
    const int wid  = tid >> 5;
    const int lane = tid & 31;
    const int bm = blockIdx.y * 128;
    const int bn = blockIdx.x * 128;
    const int KT = K >> 6;

    const int m0 = (wid & 3) * 32;
    const int n0 = (wid >> 2) * 64;

    float acc[2][8][4];
#pragma unroll
    for (int mt = 0; mt < 2; mt++)
#pragma unroll
        for (int nt = 0; nt < 8; nt++)
#pragma unroll
            for (int j = 0; j < 4; j++) acc[mt][nt][j] = 0.f;

    load_stage(sb, A, B, K, bm, bn, 0, tid);
    cp_commit();
    load_stage(sb + STAGE_B, A, B, K, bm, bn, 64, tid);
    cp_commit();

    const int arow = lane & 15;
    const int ak   = lane >> 4;
    const int brow = (lane & 7) + ((lane >> 4) & 1) * 8;
    const int bk   = (lane >> 3) & 1;

    for (int i = 0; i < KT; i++) {
        cp_wait<1>();
        __syncthreads();

        if (i + 2 < KT)
            load_stage(sb + ((i + 2) % 3) * STAGE_B, A, B,
                       K, bm, bn, (i + 2) * 64, tid);
        cp_commit();

        const uint32_t s0 = sb + (i % 3) * STAGE_B;
#pragma unroll
        for (int k = 0; k < 4; k++) {
            uint32_t af[2][4], bf[8][2];
#pragma unroll
            for (int mt = 0; mt < 2; mt++) {
                const uint32_t off =
                    SWZ((uint32_t)((m0 + mt * 16 + arow) * 128 + (2 * k + ak) * 16));
                ldmx4(af[mt], s0 + off);
            }
#pragma unroll
            for (int np = 0; np < 4; np++) {
                const uint32_t off =
                    SWZ((uint32_t)((n0 + np * 16 + brow) * 128 + (2 * k + bk) * 16));
                uint32_t q[4];
                ldmx4(q, s0 + TILE_B + off);
                bf[2 * np][0] = q[0]; bf[2 * np][1] = q[1];
                bf[2 * np + 1][0] = q[2]; bf[2 * np + 1][1] = q[3];
            }
#pragma unroll
            for (int mt = 0; mt < 2; mt++)
#pragma unroll
                for (int nt = 0; nt < 8; nt++)
                    mma_fp16(acc[mt][nt], af[mt], bf[nt]);
        }
    }

#pragma unroll
    for (int mt = 0; mt < 2; mt++) {
        const int row = bm + m0 + mt * 16 + (lane >> 2);
#pragma unroll
        for (int nt = 0; nt < 8; nt++) {
            const int col = bn + n0 + nt * 8 + (lane & 3) * 2;
            float2* p0 = (float2*)&C[(size_t)row * N + col];
            float2* p1 = (float2*)&C[(size_t)(row + 8) * N + col];
            *p0 = make_float2(acc[mt][nt][0], acc[mt][nt][1]);
            *p1 = make_float2(acc[mt][nt][2], acc[mt][nt][3]);
        }
    }
}

// ---------------------------------------------------------------------------
__global__ __launch_bounds__(256) void cvt_fp16_kernel(
    const float* __restrict__ in, __half* __restrict__ out, int n4)
{
    const int i = blockIdx.x * 256 + threadIdx.x;
    if (i >= n4) return;
    const float4 v = ((const float4*)in)[i];
    __half2* p = (__half2*)(out + (size_t)i * 4);
    p[0] = __floats2half2_rn(v.x, v.y);
    p[1] = __floats2half2_rn(v.z, v.w);
}

// ---------------------------------------------------------------------------
__global__ void zero_s_kernel()
{
    int i = blockIdx.x * 256 + threadIdx.x;
    if (i < BATCH * INTER) g_s[i] = 0.f;
}

// ---------------------------------------------------------------------------
__global__ __launch_bounds__(256) void impacts_kernel(
    const float* __restrict__ w_up, float* __restrict__ out_imp)
{
    __shared__ float red[256];
    const int i = blockIdx.x;
    float acc = 0.f;
    for (int h = threadIdx.x; h < HID; h += 256) {
        const float w = w_up[(size_t)i * HID + h];
        acc += w * w;
    }
    red[threadIdx.x] = acc;
    __syncthreads();
    for (int off = 128; off > 0; off >>= 1) {
        if (threadIdx.x < off) red[threadIdx.x] += red[threadIdx.x + off];
        __syncthreads();
    }
    if (threadIdx.x == 0) {
        const float rs = red[0];
#pragma unroll
        for (int b = 0; b < BATCH; b++)
            out_imp[b * INTER + i] = sqrtf(g_s[b * INTER + i] * rs);
    }
}

// ---------------------------------------------------------------------------
extern "C" void kernel_launch(void* const* d_in, const int* in_sizes, int n_in,
                              void* d_out, int out_size)
{
    const float* x      = (const float*)d_in[0];
    const float* w_gate = (const float*)d_in[1];
    const float* w_up   = (const float*)d_in[2];
    const float* w_down = (const float*)d_in[3];
    float* out = (float*)d_out;

    __half *xh, *wgh, *wuh, *wdh, *ifp;
    cudaGetSymbolAddress((void**)&xh,  g_xh);
    cudaGetSymbolAddress((void**)&wgh, g_wgh);
    cudaGetSymbolAddress((void**)&wuh, g_wuh);
    cudaGetSymbolAddress((void**)&wdh, g_wdh);
    cudaGetSymbolAddress((void**)&ifp, g_if);

    cudaFuncSetAttribute(gateup_fused,
                         cudaFuncAttributeMaxDynamicSharedMemorySize, FUSED_SMEM);
    cudaFuncSetAttribute(gemm_fp16,
                         cudaFuncAttributeMaxDynamicSharedMemorySize, GEMM_SMEM);

    zero_s_kernel<<<(BATCH * INTER + 255) / 256, 256>>>();

    {
        const int nx4 = MROWS * HID / 4;
        cvt_fp16_kernel<<<(nx4 + 255) / 256, 256>>>(x, xh, nx4);
        const int nw4 = INTER * HID / 4;
        cvt_fp16_kernel<<<(nw4 + 255) / 256, 256>>>(w_gate, wgh, nw4);
        cvt_fp16_kernel<<<(nw4 + 255) / 256, 256>>>(w_up, wuh, nw4);
        cvt_fp16_kernel<<<(nw4 + 255) / 256, 256>>>(w_down, wdh, nw4);
    }

    // fused: inter = silu(x@wg^T)*(x@wu^T) -> fp16 ; s += inter^2
    {
        dim3 grid(INTER / 128, MROWS / 128);
        gateup_fused<<<grid, 256, FUSED_SMEM>>>(xh, wgh, wuh);
    }

    // out = inter @ w_down^T  (M=8192, N=2048, K=5504)
    {
        dim3 grid(HID / 128, MROWS / 128);
        gemm_fp16<<<grid, 256, GEMM_SMEM>>>(ifp, wdh, out, HID, INTER);
    }

    impacts_kernel<<<INTER, 256>>>(w_up, out + (size_t)MROWS * HID);
}